// round 5
// baseline (speedup 1.0000x reference)
#include <cuda_runtime.h>
#include <math.h>

// ---------------- problem constants ----------------
#define B_  2
#define S_  4096
#define D_  768
#define H_  12
#define DH_ 64
#define L_  2
#define F_  3072
#define C_  256
#define M_  (B_*S_)
#define NEGV (-1000000000.0f)

// ---------------- scratch ----------------
__device__ float g_h  [M_ * D_];
__device__ float g_q  [M_ * D_];
__device__ float g_k  [M_ * D_];
__device__ float g_v  [M_ * D_];
__device__ float g_ctx[M_ * D_];
__device__ float g_t  [M_ * D_];
__device__ float g_f  [M_ * F_];

// ---------------- helpers ----------------
__device__ __forceinline__ float warp_sum(float v) {
    #pragma unroll
    for (int o = 16; o; o >>= 1) v += __shfl_xor_sync(0xffffffffu, v, o);
    return v;
}
__device__ __forceinline__ float warp_max(float v) {
    #pragma unroll
    for (int o = 16; o; o >>= 1) v = fmaxf(v, __shfl_xor_sync(0xffffffffu, v, o));
    return v;
}
__device__ float block_sum(float v, float* red) {
    int lane = threadIdx.x & 31, w = threadIdx.x >> 5;
    v = warp_sum(v);
    __syncthreads();
    if (lane == 0) red[w] = v;
    __syncthreads();
    int nw = (blockDim.x + 31) >> 5;
    float r = (threadIdx.x < nw) ? red[threadIdx.x] : 0.0f;
    if (w == 0) { r = warp_sum(r); if (lane == 0) red[0] = r; }
    __syncthreads();
    return red[0];
}
__device__ float block_max(float v, float* red) {
    int lane = threadIdx.x & 31, w = threadIdx.x >> 5;
    v = warp_max(v);
    __syncthreads();
    if (lane == 0) red[w] = v;
    __syncthreads();
    int nw = (blockDim.x + 31) >> 5;
    float r = (threadIdx.x < nw) ? red[threadIdx.x] : -INFINITY;
    if (w == 0) { r = warp_max(r); if (lane == 0) red[0] = r; }
    __syncthreads();
    return red[0];
}

__device__ __forceinline__ float f2tff(float v) {
    unsigned r; asm("cvt.rna.tf32.f32 %0, %1;" : "=r"(r) : "f"(v));
    return __uint_as_float(r);
}
__device__ __forceinline__ unsigned f2tf(float v) {
    unsigned r; asm("cvt.rna.tf32.f32 %0, %1;" : "=r"(r) : "f"(v)); return r;
}
__device__ __forceinline__ void mma_tf32(float* c, const unsigned* a, const unsigned* b) {
    asm volatile(
        "mma.sync.aligned.m16n8k8.row.col.f32.tf32.tf32.f32 "
        "{%0,%1,%2,%3},{%4,%5,%6,%7},{%8,%9},{%0,%1,%2,%3};\n"
        : "+f"(c[0]), "+f"(c[1]), "+f"(c[2]), "+f"(c[3])
        : "r"(a[0]), "r"(a[1]), "r"(a[2]), "r"(a[3]), "r"(b[0]), "r"(b[1]));
}
__device__ __forceinline__ void cp_async16(unsigned smem, const void* g) {
    asm volatile("cp.async.ca.shared.global [%0], [%1], 16;\n" :: "r"(smem), "l"(g));
}

// ---------------- embedding + layernorm (tf32-rounded output) ----------------
__global__ void embed_ln_kernel(const int* __restrict__ ids,
                                const float* __restrict__ tok,
                                const float* __restrict__ pos,
                                const float* __restrict__ g,
                                const float* __restrict__ be,
                                float* __restrict__ out) {
    __shared__ float red[32];
    int row = blockIdx.x;
    int s = row % S_;
    int id = ids[row];
    const float* tp = tok + (size_t)id * D_;
    const float* pp = pos + (size_t)s  * D_;
    float vals[3]; float lsum = 0.0f;
    #pragma unroll
    for (int i = 0; i < 3; i++) {
        int c = threadIdx.x + i * 256;
        vals[i] = tp[c] + pp[c];
        lsum += vals[i];
    }
    float mean = block_sum(lsum, red) * (1.0f / D_);
    float lv = 0.0f;
    #pragma unroll
    for (int i = 0; i < 3; i++) { float d = vals[i] - mean; lv += d * d; }
    float var = block_sum(lv, red) * (1.0f / D_);
    float inv = rsqrtf(var + 1e-5f);
    float* op = out + (size_t)row * D_;
    #pragma unroll
    for (int i = 0; i < 3; i++) {
        int c = threadIdx.x + i * 256;
        op[c] = f2tff((vals[i] - mean) * inv * g[c] + be[c]);
    }
}

// ---------------- residual add + layernorm (tf32-rounded output) ----------------
__global__ void add_ln_kernel(const float* __restrict__ x,
                              const float* __restrict__ r,
                              const float* __restrict__ g,
                              const float* __restrict__ be,
                              float* __restrict__ out) {
    __shared__ float red[32];
    int row = blockIdx.x;
    const float* xp = x + (size_t)row * D_;
    const float* rp = r + (size_t)row * D_;
    float vals[3]; float lsum = 0.0f;
    #pragma unroll
    for (int i = 0; i < 3; i++) {
        int c = threadIdx.x + i * 256;
        vals[i] = xp[c] + rp[c];
        lsum += vals[i];
    }
    float mean = block_sum(lsum, red) * (1.0f / D_);
    float lv = 0.0f;
    #pragma unroll
    for (int i = 0; i < 3; i++) { float d = vals[i] - mean; lv += d * d; }
    float var = block_sum(lv, red) * (1.0f / D_);
    float inv = rsqrtf(var + 1e-5f);
    float* op = out + (size_t)row * D_;
    #pragma unroll
    for (int i = 0; i < 3; i++) {
        int c = threadIdx.x + i * 256;
        op[c] = f2tff((vals[i] - mean) * inv * g[c] + be[c]);
    }
}

// ---------------- tf32 mma GEMM, 128x64 tile, 128 threads ----------------
// A (activations) is already tf32-rounded; only W is cvt'd (store path).
// A smem: [m][k] natural (cp.async), stride 20. B smem: [n][k] transposed,
// stride 20, 16B-chunk XOR swizzle by (n>>3)&3.
// k-slot remap: ks0 covers k = {4t, 4t+1}, ks1 = {4t+2, 4t+3} per thread t,
// so fragments are single LDS.128 per row / per n.
#define GSTR 20

__global__ __launch_bounds__(128, 4) void gemm_tf32_kernel(
        const float* __restrict__ A, const float* __restrict__ W,
        const float* __restrict__ bias, float* __restrict__ Co,
        int M, int N, int K, int act, float scale) {
    __shared__ unsigned As[2][128 * GSTR];
    __shared__ unsigned Bs[2][64 * GSTR];

    int tid = threadIdx.x;
    int lane = tid & 31, wid = tid >> 5;
    int gid = lane >> 2, ti = lane & 3;
    int wm = wid * 32;
    size_t rowBase = (size_t)blockIdx.y * 128;
    size_t colBase = (size_t)blockIdx.x * 64;

    // B staging slots
    int bn = tid & 63, bkh = (tid >> 6) * 8;
    int bsw = (bn >> 3) & 3;
    int bc0 = (bkh >> 2) ^ bsw;
    int bc1 = ((bkh >> 2) + 1) ^ bsw;

    float c[2][8][4];
    #pragma unroll
    for (int mi = 0; mi < 2; mi++)
        #pragma unroll
        for (int ni = 0; ni < 8; ni++)
            #pragma unroll
            for (int q = 0; q < 4; q++) c[mi][ni][q] = 0.0f;

    int nt = K / 16;
    unsigned breg[8];

    // ---- prologue: tile 0 ----
    #pragma unroll
    for (int p = 0; p < 4; p++) {
        int s = tid + p * 128;
        int row = s >> 2, ch = s & 3;
        unsigned sa = (unsigned)__cvta_generic_to_shared(&As[0][row * GSTR + ch * 4]);
        cp_async16(sa, &A[(rowBase + row) * K + ch * 4]);
    }
    asm volatile("cp.async.commit_group;\n");
    #pragma unroll
    for (int kk = 0; kk < 8; kk++)
        breg[kk] = f2tf(W[(size_t)(bkh + kk) * N + colBase + bn]);
    *(uint4*)&Bs[0][bn * GSTR + bc0 * 4] = make_uint4(breg[0], breg[1], breg[2], breg[3]);
    *(uint4*)&Bs[0][bn * GSTR + bc1 * 4] = make_uint4(breg[4], breg[5], breg[6], breg[7]);
    asm volatile("cp.async.wait_group 0;\n");
    __syncthreads();

    for (int kt = 0; kt < nt; kt++) {
        int cur = kt & 1, nxt = cur ^ 1;
        bool hasNext = (kt + 1) < nt;
        if (hasNext) {
            int k0n = (kt + 1) * 16;
            #pragma unroll
            for (int p = 0; p < 4; p++) {
                int s = tid + p * 128;
                int row = s >> 2, ch = s & 3;
                unsigned sa = (unsigned)__cvta_generic_to_shared(&As[nxt][row * GSTR + ch * 4]);
                cp_async16(sa, &A[(rowBase + row) * K + k0n + ch * 4]);
            }
            asm volatile("cp.async.commit_group;\n");
            #pragma unroll
            for (int kk = 0; kk < 8; kk++)
                breg[kk] = f2tf(W[(size_t)(k0n + bkh + kk) * N + colBase + bn]);
        }

        // fragments + mma
        uint4 a4[2][2];
        #pragma unroll
        for (int mi = 0; mi < 2; mi++)
            #pragma unroll
            for (int rh = 0; rh < 2; rh++)
                a4[mi][rh] = *(uint4*)&As[cur][(wm + mi * 16 + rh * 8 + gid) * GSTR + ti * 4];

        #pragma unroll
        for (int ni = 0; ni < 8; ni++) {
            uint4 b4 = *(uint4*)&Bs[cur][(ni * 8 + gid) * GSTR + ((ti ^ (ni & 3)) * 4)];
            unsigned bb0[2] = {b4.x, b4.y};
            unsigned bb1[2] = {b4.z, b4.w};
            #pragma unroll
            for (int mi = 0; mi < 2; mi++) {
                unsigned aa0[4] = {a4[mi][0].x, a4[mi][1].x, a4[mi][0].y, a4[mi][1].y};
                mma_tf32(c[mi][ni], aa0, bb0);
                unsigned aa1[4] = {a4[mi][0].z, a4[mi][1].z, a4[mi][0].w, a4[mi][1].w};
                mma_tf32(c[mi][ni], aa1, bb1);
            }
        }

        if (hasNext) {
            *(uint4*)&Bs[nxt][bn * GSTR + bc0 * 4] = make_uint4(breg[0], breg[1], breg[2], breg[3]);
            *(uint4*)&Bs[nxt][bn * GSTR + bc1 * 4] = make_uint4(breg[4], breg[5], breg[6], breg[7]);
            asm volatile("cp.async.wait_group 0;\n");
        }
        __syncthreads();
    }

    // epilogue (tf32-rounded output)
    #pragma unroll
    for (int mi = 0; mi < 2; mi++) {
        size_t r0 = rowBase + wm + mi * 16 + gid;
        size_t r1 = r0 + 8;
        #pragma unroll
        for (int ni = 0; ni < 8; ni++) {
            size_t col = colBase + ni * 8 + ti * 2;
            float b0 = bias[col], b1 = bias[col + 1];
            float v0 = (c[mi][ni][0] + b0) * scale;
            float v1 = (c[mi][ni][1] + b1) * scale;
            float v2 = (c[mi][ni][2] + b0) * scale;
            float v3 = (c[mi][ni][3] + b1) * scale;
            if (act == 1) {
                v0 = 0.5f * v0 * (1.0f + erff(v0 * 0.70710678f));
                v1 = 0.5f * v1 * (1.0f + erff(v1 * 0.70710678f));
                v2 = 0.5f * v2 * (1.0f + erff(v2 * 0.70710678f));
                v3 = 0.5f * v3 * (1.0f + erff(v3 * 0.70710678f));
            }
            *(float2*)&Co[r0 * N + col] = make_float2(f2tff(v0), f2tff(v1));
            *(float2*)&Co[r1 * N + col] = make_float2(f2tff(v2), f2tff(v3));
        }
    }
}

// ---------------- sliding-window attention (tensor-core) ----------------
#define SCW2 772
#define AT_Q   0
#define AT_KV  2176
#define AT_SC  6528
#define AT_INV 31232
#define AT_MV  31264
#define AT_SMEM ((31328) * 4)

__global__ __launch_bounds__(256) void sw_attn_kernel(
        const float* __restrict__ q,
        const float* __restrict__ k,
        const float* __restrict__ v,
        const int* __restrict__ mask,
        float* __restrict__ ctx) {
    extern __shared__ float sm[];
    unsigned* qU  = (unsigned*)(sm + AT_Q);
    unsigned* kvU = (unsigned*)(sm + AT_KV);
    float* sc  = sm + AT_SC;
    float* inv = sm + AT_INV;
    float* mv  = sm + AT_MV;
    unsigned* scU = (unsigned*)sc;

    int tid = threadIdx.x;
    int lane = tid & 31, w = tid >> 5;
    int gid = lane >> 2, ti = lane & 3;
    int h = blockIdx.y, b = blockIdx.z;
    int qbase = blockIdx.x * 32;
    int n = qbase / C_;
    int cbase = qbase % C_;
    int j0 = (n - 1) * C_;
    int n0 = w * 8;

    #pragma unroll
    for (int p = 0; p < 2; p++) {
        int s = tid + p * 256;
        int r = s >> 4, c4 = (s & 15) * 4;
        float4 qv = *(const float4*)&q[((size_t)(b * S_ + qbase + r)) * D_ + h * DH_ + c4];
        qU[r * 68 + c4 + 0] = f2tf(qv.x);
        qU[r * 68 + c4 + 1] = f2tf(qv.y);
        qU[r * 68 + c4 + 2] = f2tf(qv.z);
        qU[r * 68 + c4 + 3] = f2tf(qv.w);
    }
    __syncthreads();

    unsigned aF[2][8][4];
    #pragma unroll
    for (int mi = 0; mi < 2; mi++)
        #pragma unroll
        for (int ks = 0; ks < 8; ks++) {
            const unsigned* ap = &qU[(mi * 16 + gid) * 68 + ks * 8 + ti];
            aF[mi][ks][0] = ap[0];
            aF[mi][ks][1] = ap[8 * 68];
            aF[mi][ks][2] = ap[4];
            aF[mi][ks][3] = ap[8 * 68 + 4];
        }

    for (int kt = 0; kt < 12; kt++) {
        __syncthreads();
        #pragma unroll
        for (int p = 0; p < 4; p++) {
            int s = tid + p * 256;
            int r = s >> 4, c4 = (s & 15) * 4;
            int j = j0 + kt * 64 + r;
            float4 kvv = make_float4(0.f, 0.f, 0.f, 0.f);
            if (j >= 0 && j < S_)
                kvv = *(const float4*)&k[((size_t)(b * S_ + j)) * D_ + h * DH_ + c4];
            unsigned* kp = &kvU[r * 68 + c4];
            kp[0] = f2tf(kvv.x); kp[1] = f2tf(kvv.y);
            kp[2] = f2tf(kvv.z); kp[3] = f2tf(kvv.w);
            if (c4 == 0)
                mv[r] = (j > 0 && j < S_ && mask[b * S_ + j] > 0) ? 1.0f : 0.0f;
        }
        __syncthreads();

        float cS[2][4];
        #pragma unroll
        for (int mi = 0; mi < 2; mi++)
            #pragma unroll
            for (int qq = 0; qq < 4; qq++) cS[mi][qq] = 0.0f;

        #pragma unroll
        for (int ks = 0; ks < 8; ks++) {
            unsigned bb[2];
            bb[0] = kvU[(n0 + gid) * 68 + ks * 8 + ti];
            bb[1] = kvU[(n0 + gid) * 68 + ks * 8 + ti + 4];
            mma_tf32(cS[0], aF[0][ks], bb);
            mma_tf32(cS[1], aF[1][ks], bb);
        }

        int kk0 = kt * 64 + n0 + 2 * ti;
        float valid0 = mv[n0 + 2 * ti], valid1 = mv[n0 + 2 * ti + 1];
        #pragma unroll
        for (int mi = 0; mi < 2; mi++) {
            int r0 = mi * 16 + gid, r1 = r0 + 8;
            int cq0 = cbase + r0, cq1 = cbase + r1;
            bool ok00 = (valid0 > 0.5f) && (kk0 >= cq0) && (kk0 <= cq0 + 2 * C_);
            bool ok01 = (valid1 > 0.5f) && (kk0 + 1 >= cq0) && (kk0 + 1 <= cq0 + 2 * C_);
            bool ok10 = (valid0 > 0.5f) && (kk0 >= cq1) && (kk0 <= cq1 + 2 * C_);
            bool ok11 = (valid1 > 0.5f) && (kk0 + 1 >= cq1) && (kk0 + 1 <= cq1 + 2 * C_);
            sc[r0 * SCW2 + kk0]     = ok00 ? cS[mi][0] : NEGV;
            sc[r0 * SCW2 + kk0 + 1] = ok01 ? cS[mi][1] : NEGV;
            sc[r1 * SCW2 + kk0]     = ok10 ? cS[mi][2] : NEGV;
            sc[r1 * SCW2 + kk0 + 1] = ok11 ? cS[mi][3] : NEGV;
        }
    }

    if (tid < 32) {
        float acc = 0.0f;
        const float* k0p = k + ((size_t)(b * S_)) * D_ + h * DH_;
        #pragma unroll 8
        for (int d = 0; d < 64; d++)
            acc = fmaf(__uint_as_float(qU[tid * 68 + d]), k0p[d], acc);
        sc[tid * SCW2 + 3 * C_] = (mask[b * S_] > 0) ? acc : NEGV;
    }
    __syncthreads();

    for (int rr = 0; rr < 4; rr++) {
        int qi = w + rr * 8;
        float* row = sc + qi * SCW2;
        float m = -INFINITY;
        for (int j = lane; j < 3 * C_ + 1; j += 32) m = fmaxf(m, row[j]);
        m = warp_max(m);
        float ssum = 0.0f;
        for (int j = lane; j < 3 * C_ + 1; j += 32) {
            float e = __expf(row[j] - m);
            ssum += e;
            row[j] = __uint_as_float(f2tf(e));
        }
        ssum = warp_sum(ssum);
        if (lane == 0) inv[qi] = 1.0f / ssum;
    }

    float cO[2][4];
    #pragma unroll
    for (int mi = 0; mi < 2; mi++)
        #pragma unroll
        for (int qq = 0; qq < 4; qq++) cO[mi][qq] = 0.0f;

    for (int kt = 0; kt < 12; kt++) {
        __syncthreads();
        #pragma unroll
        for (int p = 0; p < 4; p++) {
            int s = tid + p * 256;
            int r = s >> 4, c4 = (s & 15) * 4;
            int j = j0 + kt * 64 + r;
            float4 vv = make_float4(0.f, 0.f, 0.f, 0.f);
            if (j >= 0 && j < S_)
                vv = *(const float4*)&v[((size_t)(b * S_ + j)) * D_ + h * DH_ + c4];
            kvU[(c4 + 0) * 68 + (r ^ ((c4 + 0) >> 3))] = f2tf(vv.x);
            kvU[(c4 + 1) * 68 + (r ^ ((c4 + 1) >> 3))] = f2tf(vv.y);
            kvU[(c4 + 2) * 68 + (r ^ ((c4 + 2) >> 3))] = f2tf(vv.z);
            kvU[(c4 + 3) * 68 + (r ^ ((c4 + 3) >> 3))] = f2tf(vv.w);
        }
        __syncthreads();

        #pragma unroll
        for (int ks = 0; ks < 8; ks++) {
            unsigned bb[2];
            int drow = n0 + gid;
            bb[0] = kvU[drow * 68 + ((ks * 8 + ti) ^ w)];
            bb[1] = kvU[drow * 68 + ((ks * 8 + ti + 4) ^ w)];
            #pragma unroll
            for (int mi = 0; mi < 2; mi++) {
                unsigned aa[4];
                const unsigned* pp = &scU[(mi * 16 + gid) * SCW2 + kt * 64 + ks * 8 + ti];
                aa[0] = pp[0];
                aa[1] = pp[8 * SCW2];
                aa[2] = pp[4];
                aa[3] = pp[8 * SCW2 + 4];
                mma_tf32(cO[mi], aa, bb);
            }
        }
    }

    {
        const float* v0p = v + ((size_t)(b * S_)) * D_ + h * DH_;
        int d0 = n0 + 2 * ti;
        float gv0 = v0p[d0], gv1 = v0p[d0 + 1];
        #pragma unroll
        for (int mi = 0; mi < 2; mi++) {
            int r0 = mi * 16 + gid, r1 = r0 + 8;
            float g0 = sc[r0 * SCW2 + 3 * C_], g1 = sc[r1 * SCW2 + 3 * C_];
            float i0 = inv[r0], i1 = inv[r1];
            float2 o0 = make_float2(f2tff((cO[mi][0] + g0 * gv0) * i0),
                                    f2tff((cO[mi][1] + g0 * gv1) * i0));
            float2 o1 = make_float2(f2tff((cO[mi][2] + g1 * gv0) * i1),
                                    f2tff((cO[mi][3] + g1 * gv1) * i1));
            *(float2*)&ctx[((size_t)(b * S_ + qbase + r0)) * D_ + h * DH_ + d0] = o0;
            *(float2*)&ctx[((size_t)(b * S_ + qbase + r1)) * D_ + h * DH_ + d0] = o1;
        }
    }
}

// ---------------- full attention for query row 0 ----------------
__global__ void global_attn_kernel(const float* __restrict__ q,
                                   const float* __restrict__ k,
                                   const float* __restrict__ v,
                                   const int* __restrict__ mask,
                                   float* __restrict__ ctx) {
    __shared__ float qs[64];
    __shared__ float sc[S_];
    __shared__ float red[32];
    __shared__ float cpart[256];
    int h = blockIdx.x, b = blockIdx.y;
    int tid = threadIdx.x;
    const float* qp = q + ((size_t)(b * S_)) * D_ + h * DH_;
    if (tid < 16) ((float4*)qs)[tid] = ((const float4*)qp)[tid];
    __syncthreads();

    for (int j = tid; j < S_; j += 256) {
        float s = NEGV;
        if (mask[b * S_ + j] > 0) {
            const float4* kp = (const float4*)(k + ((size_t)(b * S_ + j)) * D_ + h * DH_);
            float acc = 0.0f;
            #pragma unroll
            for (int d4 = 0; d4 < 16; d4++) {
                float4 kvv = kp[d4];
                float4 qv = ((const float4*)qs)[d4];
                acc += kvv.x * qv.x + kvv.y * qv.y + kvv.z * qv.z + kvv.w * qv.w;
            }
            s = acc;
        }
        sc[j] = s;
    }
    __syncthreads();

    float m = -INFINITY;
    for (int j = tid; j < S_; j += 256) m = fmaxf(m, sc[j]);
    m = block_max(m, red);
    float lsum = 0.0f;
    for (int j = tid; j < S_; j += 256) {
        float e = __expf(sc[j] - m);
        sc[j] = e;
        lsum += e;
    }
    float sum = block_sum(lsum, red);
    float inv = 1.0f / sum;

    int d = tid & 63, part = tid >> 6;
    float accum = 0.0f;
    for (int j = part; j < S_; j += 4)
        accum += sc[j] * v[((size_t)(b * S_ + j)) * D_ + h * DH_ + d];
    cpart[tid] = accum;
    __syncthreads();
    if (part == 0)
        ctx[((size_t)(b * S_)) * D_ + h * DH_ + d] =
            f2tff((cpart[d] + cpart[64 + d] + cpart[128 + d] + cpart[192 + d]) * inv);
}

// ---------------- classifier head ----------------
__global__ void cls_kernel(const float* __restrict__ h,
                           const float* __restrict__ W,
                           const float* __restrict__ bias,
                           float* __restrict__ out) {
    int w = threadIdx.x >> 5, lane = threadIdx.x & 31;
    if (w < B_ * 3) {
        int b = w / 3, c = w % 3;
        float acc = 0.0f;
        for (int kx = lane; kx < D_; kx += 32)
            acc += h[((size_t)(b * S_)) * D_ + kx] * W[kx * 3 + c];
        acc = warp_sum(acc);
        if (lane == 0) out[b * 3 + c] = acc + bias[c];
    }
}

// ---------------- launch ----------------
extern "C" void kernel_launch(void* const* d_in, const int* in_sizes, int n_in,
                              void* d_out, int out_size) {
    const int*   ids      = (const int*)d_in[0];
    const int*   mask     = (const int*)d_in[1];
    const float* emb_tok  = (const float*)d_in[2];
    const float* emb_pos  = (const float*)d_in[3];
    const float* emb_ln_g = (const float*)d_in[4];
    const float* emb_ln_b = (const float*)d_in[5];
    const float* Wq = (const float*)d_in[6];
    const float* bq = (const float*)d_in[7];
    const float* Wk = (const float*)d_in[8];
    const float* bk = (const float*)d_in[9];
    const float* Wv = (const float*)d_in[10];
    const float* bv = (const float*)d_in[11];
    const float* Wo = (const float*)d_in[12];
    const float* bo = (const float*)d_in[13];
    const float* ln1_g = (const float*)d_in[14];
    const float* ln1_b = (const float*)d_in[15];
    const float* W1 = (const float*)d_in[16];
    const float* b1 = (const float*)d_in[17];
    const float* W2 = (const float*)d_in[18];
    const float* b2 = (const float*)d_in[19];
    const float* ln2_g = (const float*)d_in[20];
    const float* ln2_b = (const float*)d_in[21];
    const float* clsW = (const float*)d_in[22];
    const float* clsb = (const float*)d_in[23];

    float *h, *q, *k, *v, *ctx, *t, *f;
    cudaGetSymbolAddress((void**)&h,   g_h);
    cudaGetSymbolAddress((void**)&q,   g_q);
    cudaGetSymbolAddress((void**)&k,   g_k);
    cudaGetSymbolAddress((void**)&v,   g_v);
    cudaGetSymbolAddress((void**)&ctx, g_ctx);
    cudaGetSymbolAddress((void**)&t,   g_t);
    cudaGetSymbolAddress((void**)&f,   g_f);

    static int attr_done = 0;
    if (!attr_done) {
        cudaFuncSetAttribute(sw_attn_kernel,
                             cudaFuncAttributeMaxDynamicSharedMemorySize, AT_SMEM);
        attr_done = 1;
    }

    embed_ln_kernel<<<M_, 256>>>(ids, emb_tok, emb_pos, emb_ln_g, emb_ln_b, h);

    for (int l = 0; l < L_; l++) {
        const float* Wql = Wq + (size_t)l * D_ * D_;
        const float* Wkl = Wk + (size_t)l * D_ * D_;
        const float* Wvl = Wv + (size_t)l * D_ * D_;
        const float* Wol = Wo + (size_t)l * D_ * D_;
        const float* W1l = W1 + (size_t)l * D_ * F_;
        const float* W2l = W2 + (size_t)l * F_ * D_;

        dim3 gD(D_ / 64, M_ / 128);
        dim3 gF(F_ / 64, M_ / 128);

        gemm_tf32_kernel<<<gD, 128>>>(h, Wql, bq + l * D_, q, M_, D_, D_, 0, 0.125f);
        gemm_tf32_kernel<<<gD, 128>>>(h, Wkl, bk + l * D_, k, M_, D_, D_, 0, 1.0f);
        gemm_tf32_kernel<<<gD, 128>>>(h, Wvl, bv + l * D_, v, M_, D_, D_, 0, 1.0f);

        sw_attn_kernel<<<dim3(S_ / 32, H_, B_), 256, AT_SMEM>>>(q, k, v, mask, ctx);
        global_attn_kernel<<<dim3(H_, B_), 256>>>(q, k, v, mask, ctx);

        gemm_tf32_kernel<<<gD, 128>>>(ctx, Wol, bo + l * D_, t, M_, D_, D_, 0, 1.0f);
        add_ln_kernel<<<M_, 256>>>(h, t, ln1_g + l * D_, ln1_b + l * D_, h);

        gemm_tf32_kernel<<<gF, 128>>>(h, W1l, b1 + l * F_, f, M_, F_, D_, 1, 1.0f);
        gemm_tf32_kernel<<<gD, 128>>>(f, W2l, b2 + l * D_, t, M_, D_, F_, 0, 1.0f);
        add_ln_kernel<<<M_, 256>>>(h, t, ln2_g + l * D_, ln2_b + l * D_, h);
    }

    cls_kernel<<<1, 256>>>(h, clsW, clsb, (float*)d_out);
}